// round 15
// baseline (speedup 1.0000x reference)
#include <cuda_runtime.h>
#include <cuda_fp16.h>
#include <cuda_bf16.h>
#include <math.h>

#define NMAX 50000
#define DIM 128
#define KNBR 16
#define HSW 68            // smem row stride in 32-bit words (64 data + 4 pad)
#define STAGE_BYTES 32768 // one 8-row gather group: 8*16*256B

// Scratch (static device globals — no allocation allowed)
__device__ __half g_E [(size_t)NMAX * DIM];
__device__ __half g_H1[(size_t)NMAX * DIM];
__device__ __half g_C [(size_t)NMAX * 2 * DIM];
__device__ __half g_Wh[256 * 128];   // Wcat^T as [n][k] fp16, row-major

// ---------------------------------------------------------------------------
// PREP: fp32->fp16 embedding convert + Wcat^T fp16 prep + zero loss accum.
// ---------------------------------------------------------------------------
__global__ void prep_kernel(const float* __restrict__ in, __half* __restrict__ out,
                            int n4, const float* __restrict__ W1,
                            __half* __restrict__ Wh,
                            float* __restrict__ loss_out, int loss_n) {
    int i = blockIdx.x * blockDim.x + threadIdx.x;
    if (blockIdx.x == 0 && threadIdx.x < (unsigned)loss_n) loss_out[threadIdx.x] = 0.f;
    if (i < n4) {
        float4 v = __ldg((const float4*)in + i);
        __half2 lo = __floats2half2_rn(v.x, v.y);
        __half2 hi = __floats2half2_rn(v.z, v.w);
        uint2 u;
        u.x = *(unsigned*)&lo;
        u.y = *(unsigned*)&hi;
        ((uint2*)out)[i] = u;
    }
    if (i < 256 * 128) {
        int r = i >> 7;
        int c = i & 127;
        float v = __ldg(W1 + i);
        int k = r & 127;
        int n = c + ((r >> 7) << 7);
        Wh[n * 128 + k] = __float2half_rn(v);
    }
}

// ---------------------------------------------------------------------------
// Mean neighbor aggregation (layer 1), fp16: warp = 2 nodes, HADD2 accumulate.
// ---------------------------------------------------------------------------
__global__ void agg_kernel(const __half* __restrict__ in,
                           const int* __restrict__ nbr,
                           __half* __restrict__ out, int N) {
    int gw = (blockIdx.x * blockDim.x + threadIdx.x) >> 5;
    int lane = threadIdx.x & 31;
    int node = gw * 2 + (lane >> 4);
    if (node >= N) return;
    int sl = lane & 15;
    const int* nb = nbr + (size_t)node * KNBR;
    const uint4* in16 = (const uint4*)in;
    __half2 z = __float2half2_rn(0.f);
    __half2 a0 = z, a1 = z, a2 = z, a3 = z;
#pragma unroll
    for (int k = 0; k < KNBR; k++) {
        int idx = __ldg(nb + k);
        uint4 v = __ldg(in16 + (size_t)idx * 16 + sl);
        a0 = __hadd2(a0, *(__half2*)&v.x);
        a1 = __hadd2(a1, *(__half2*)&v.y);
        a2 = __hadd2(a2, *(__half2*)&v.z);
        a3 = __hadd2(a3, *(__half2*)&v.w);
    }
    __half2 s = __float2half2_rn(1.0f / (float)KNBR);
    a0 = __hmul2(a0, s); a1 = __hmul2(a1, s);
    a2 = __hmul2(a2, s); a3 = __hmul2(a3, s);
    uint4 r;
    r.x = *(unsigned*)&a0; r.y = *(unsigned*)&a1;
    r.z = *(unsigned*)&a2; r.w = *(unsigned*)&a3;
    ((uint4*)out)[(size_t)node * 16 + sl] = r;
}

// ---------------------------------------------------------------------------
// fp16 MMA + ldmatrix + cp.async helpers
// ---------------------------------------------------------------------------
__device__ __forceinline__ void mma_f16(float* d, const unsigned* a, const unsigned* b) {
    asm("mma.sync.aligned.m16n8k16.row.col.f32.f16.f16.f32 "
        "{%0,%1,%2,%3}, {%4,%5,%6,%7}, {%8,%9}, {%0,%1,%2,%3};"
        : "+f"(d[0]), "+f"(d[1]), "+f"(d[2]), "+f"(d[3])
        : "r"(a[0]), "r"(a[1]), "r"(a[2]), "r"(a[3]), "r"(b[0]), "r"(b[1]));
}

__device__ __forceinline__ void ldsm_x4(unsigned* r, unsigned addr) {
    asm volatile("ldmatrix.sync.aligned.m8n8.x4.shared.b16 {%0,%1,%2,%3}, [%4];"
                 : "=r"(r[0]), "=r"(r[1]), "=r"(r[2]), "=r"(r[3]) : "r"(addr));
}

// Issue one 8-row gather group via cp.async: 2048 x 16B, 4 per thread.
__device__ __forceinline__ void issue_group(unsigned stage_base, const int* snbr,
                                            const char* H1c, int grp, int t) {
    unsigned buf = stage_base + (unsigned)(grp % 3) * STAGE_BYTES;
#pragma unroll
    for (int j = 0; j < 4; j++) {
        int i = t + j * 512;
        int row8 = i >> 8;
        int rem = i & 255;
        int nb = rem >> 4;
        int c16 = rem & 15;
        int idx = snbr[(grp * 8 + row8) * 16 + nb];
        unsigned dst = buf + (unsigned)((row8 * 16 + nb) << 8) + (unsigned)(c16 << 4);
        const char* src = H1c + ((size_t)idx << 8) + (c16 << 4);
        asm volatile("cp.async.cg.shared.global [%0], [%1], 16;"
                     :: "r"(dst), "l"(src) : "memory");
    }
    asm volatile("cp.async.commit_group;" ::: "memory");
}

// Reduce one staged group: warps 0-7, warp w reduces row w (lane owns 8B).
__device__ __forceinline__ void reduce_group(const char* stage, unsigned* Hn,
                                             int grp, int warp, int lane,
                                             __half2 hscale) {
    if (warp < 8) {
        const char* sb = stage + (size_t)(grp % 3) * STAGE_BYTES
                       + (size_t)warp * 16 * 256 + (size_t)lane * 8;
        __half2 s0 = __float2half2_rn(0.f), s1 = s0;
#pragma unroll
        for (int k = 0; k < 16; k++) {
            uint2 v = *(const uint2*)(sb + k * 256);
            s0 = __hadd2(s0, *(__half2*)&v.x);
            s1 = __hadd2(s1, *(__half2*)&v.y);
        }
        s0 = __hmul2(s0, hscale);
        s1 = __hmul2(s1, hscale);
        int r_local = grp * 8 + warp;
        uint2 o;
        o.x = *(unsigned*)&s0;
        o.y = *(unsigned*)&s1;
        *(uint2*)(Hn + r_local * HSW + lane * 2) = o;
    }
}

#define WAIT_GRP(grp_) do {                                                   \
    if ((grp_) <= 5)      asm volatile("cp.async.wait_group 2;" ::: "memory");\
    else if ((grp_) == 6) asm volatile("cp.async.wait_group 1;" ::: "memory");\
    else                  asm volatile("cp.async.wait_group 0;" ::: "memory");\
} while (0)

// ---------------------------------------------------------------------------
// FUSED agg-layer-2 + projection GEMM with cp.async STAGED gather.
// 1 CTA/SM x 512 threads. 16 warps: 4(m) x 4(n), warp tile 16x64, 32-reg acc.
// Smem: Ws 69.6K + Hs 2x17.4K + nbr cache 4K + stage 3x32K = 202K.
// Per tile: 8 chunk-steps; step g = wait(g) -> bar -> issue(g+2) ->
//           reduce(g, warps 0-7) -> MMA chunk g (all warps).
// ---------------------------------------------------------------------------
extern __shared__ unsigned s_dyn_u[];

__global__ __launch_bounds__(512, 1) void agg_gemm_kernel(const __half* __restrict__ H1,
                                                          const int* __restrict__ nbr,
                                                          const __half* __restrict__ Wh,
                                                          __half* __restrict__ C, int N) {
    unsigned* Ws  = s_dyn_u;                 // words; halves [256][136]
    unsigned* Hs0 = s_dyn_u + 256 * HSW;     // words; halves [64][136]
    unsigned* Hs1 = Hs0 + 64 * HSW;
    int* snbr = (int*)(Hs1 + 64 * HSW);      // 1024 ints (64 rows x 16)
    char* stage = (char*)(snbr + 1024);      // 3 x 32KB

    int t = threadIdx.x;
    int lane = t & 31;
    int warp = t >> 5;
    int mwarp = warp >> 2;      // 0..3
    int nwarp = warp & 3;       // 0..3
    int g  = lane >> 2;
    int tg = lane & 3;
    int n0 = nwarp * 64;

    // Fill Ws from pre-converted fp16 Wh[n][k] (4096 uint4, 8 per thread)
    {
        const uint4* W16 = (const uint4*)Wh;
#pragma unroll
        for (int j = 0; j < 8; j++) {
            int i = t + j * 512;
            int n = i >> 4;
            int q = i & 15;
            uint4 v = __ldg(W16 + i);
            *(uint4*)(Ws + n * HSW + q * 4) = v;
        }
    }

    unsigned hs0_b = (unsigned)__cvta_generic_to_shared(Hs0);
    unsigned hs1_b = (unsigned)__cvta_generic_to_shared(Hs1);
    unsigned ws_base = (unsigned)__cvta_generic_to_shared(Ws);
    unsigned stage_b = (unsigned)__cvta_generic_to_shared(stage);
    unsigned a_row  = lane & 15;
    unsigned a_koff = (lane >> 4) * 8;
    unsigned b_n    = (lane & 7) + ((lane >> 4) << 3);
    unsigned b_koff = ((lane >> 3) & 1) << 3;

    int numRowTiles = (N + 63) >> 6;
    int stride = gridDim.x;
    int rt0 = blockIdx.x;

    const char* H1c = (const char*)H1;
    const __half2 hscale = __float2half2_rn(1.0f / (float)KNBR);

    // ---- Prologue: staged gather of tile rt0 into Hs0 ----
    {
        if (t < 256) {
            int row = rt0 * 64 + (t >> 2);
            int cr = row < N ? row : N - 1;
            ((uint4*)snbr)[t] = __ldg((const uint4*)(nbr + (size_t)cr * KNBR) + (t & 3));
        }
        __syncthreads();
        issue_group(stage_b, snbr, H1c, 0, t);
        issue_group(stage_b, snbr, H1c, 1, t);
#pragma unroll
        for (int grp = 0; grp < 8; grp++) {
            WAIT_GRP(grp);
            __syncthreads();
            if (grp < 6) issue_group(stage_b, snbr, H1c, grp + 2, t);
            reduce_group(stage, Hs0, grp, warp, lane, hscale);
        }
    }

    int cur = 0;
    for (int rt = rt0; rt < numRowTiles; rt += stride) {
        int row0 = rt * 64;
        int rtn = rt + stride;
        const bool has_next = (rtn < numRowTiles);

        __syncthreads();   // Hs[cur] complete; snbr free; stage free

        if (has_next && t < 256) {
            int row = rtn * 64 + (t >> 2);
            int cr = row < N ? row : N - 1;
            ((uint4*)snbr)[t] = __ldg((const uint4*)(nbr + (size_t)cr * KNBR) + (t & 3));
        }
        __syncthreads();   // snbr visible

        if (has_next) {
            issue_group(stage_b, snbr, H1c, 0, t);
            issue_group(stage_b, snbr, H1c, 1, t);
        }

        unsigned hs_base = cur ? hs1_b : hs0_b;
        unsigned* Hn = cur ? Hs0 : Hs1;

        float acc[8][4];
#pragma unroll
        for (int nf = 0; nf < 8; nf++)
#pragma unroll
            for (int e = 0; e < 4; e++) acc[nf][e] = 0.f;

#pragma unroll
        for (int grp = 0; grp < 8; grp++) {
            if (has_next) WAIT_GRP(grp);
            __syncthreads();
            if (has_next && grp < 6) issue_group(stage_b, snbr, H1c, grp + 2, t);
            if (has_next) reduce_group(stage, Hn, grp, warp, lane, hscale);

            // MMA chunk grp
            unsigned k0 = grp * 16;
            unsigned af[4];
            ldsm_x4(af, hs_base + ((mwarp * 16 + a_row) * (2 * HSW) + k0 + a_koff) * 2);
            unsigned b[8][2];
#pragma unroll
            for (int j = 0; j < 4; j++) {
                unsigned addr = ws_base +
                    ((n0 + j * 16 + b_n) * (2 * HSW) + k0 + b_koff) * 2;
                unsigned r[4];
                ldsm_x4(r, addr);
                b[2 * j][0] = r[0]; b[2 * j][1] = r[1];
                b[2 * j + 1][0] = r[2]; b[2 * j + 1][1] = r[3];
            }
#pragma unroll
            for (int nf = 0; nf < 8; nf++)
                mma_f16(acc[nf], af, b[nf]);
        }

        // Epilogue -> fp16 C
        unsigned* C32 = (unsigned*)C;
        int r_lo = row0 + mwarp * 16 + g;
        int r_hi = r_lo + 8;
#pragma unroll
        for (int nf = 0; nf < 8; nf++) {
            int colh = (n0 + nf * 8 + tg * 2) >> 1;
            if (r_lo < N) {
                __half2 h = __floats2half2_rn(acc[nf][0], acc[nf][1]);
                C32[(size_t)r_lo * 128 + colh] = *(unsigned*)&h;
            }
            if (r_hi < N) {
                __half2 h = __floats2half2_rn(acc[nf][2], acc[nf][3]);
                C32[(size_t)r_hi * 128 + colh] = *(unsigned*)&h;
            }
        }
        cur ^= 1;
    }
}

// ---------------------------------------------------------------------------
// Per-pair loss: one warp = TWO pairs, lean state, software-pipelined.
// ---------------------------------------------------------------------------
__global__ void pair_kernel(const int* __restrict__ pairs,
                            const int* __restrict__ labels,
                            const __half* __restrict__ C,
                            const float* __restrict__ b1,
                            const float* __restrict__ W2,
                            const float* __restrict__ b2,
                            float* __restrict__ out, int B) {
    int lane = threadIdx.x & 31;
    int sl = lane & 15;
    int side = lane >> 4;
    int wib = threadIdx.x >> 5;
    int warpsPerBlock = blockDim.x >> 5;
    int gwarp = blockIdx.x * warpsPerBlock + wib;
    int nwarps = gridDim.x * warpsPerBlock;
    int step = nwarps * 2;

    float4 b_lo = __ldg((const float4*)b1 + 2 * sl);
    float4 b_hi = __ldg((const float4*)b1 + 2 * sl + 1);
    float bias[8] = {b_lo.x, b_lo.y, b_lo.z, b_lo.w, b_hi.x, b_hi.y, b_hi.z, b_hi.w};
    float w20[8], w21[8];
#pragma unroll
    for (int q = 0; q < 8; q++) {
        w20[q] = __ldg(W2 + (sl * 8 + q) * 2 + 0);
        w21[q] = __ldg(W2 + (sl * 8 + q) * 2 + 1);
    }
    float b2_0 = __ldg(b2 + 0), b2_1 = __ldg(b2 + 1);

    const uint4* C16 = (const uint4*)C;
    float lsum = 0.f;

    int p = gwarp * 2 + side;
    uint4 ua, ub;
    if (p < B) {
        int src = __ldg(pairs + 2 * p);
        int dst = __ldg(pairs + 2 * p + 1);
        ua = __ldg(C16 + (size_t)src * 32 + sl);
        ub = __ldg(C16 + (size_t)dst * 32 + 16 + sl);
    }

    while (p < B) {
        int pn = p + step;
        uint4 na, nb;
        if (pn < B) {
            int nsrc = __ldg(pairs + 2 * pn);
            int ndst = __ldg(pairs + 2 * pn + 1);
            na = __ldg(C16 + (size_t)nsrc * 32 + sl);
            nb = __ldg(C16 + (size_t)ndst * 32 + 16 + sl);
        }

        float l0 = 0.f, l1 = 0.f;
        const unsigned* au = (const unsigned*)&ua;
        const unsigned* bu = (const unsigned*)&ub;
#pragma unroll
        for (int c = 0; c < 4; c++) {
            float2 af = __half22float2(*(__half2*)&au[c]);
            float2 bf = __half22float2(*(__half2*)&bu[c]);
            float h0 = fmaxf(af.x + bf.x + bias[2 * c], 0.f);
            float h1 = fmaxf(af.y + bf.y + bias[2 * c + 1], 0.f);
            l0 += h0 * w20[2 * c] + h1 * w20[2 * c + 1];
            l1 += h0 * w21[2 * c] + h1 * w21[2 * c + 1];
        }
#pragma unroll
        for (int off = 8; off > 0; off >>= 1) {
            l0 += __shfl_xor_sync(0xFFFFFFFFu, l0, off);
            l1 += __shfl_xor_sync(0xFFFFFFFFu, l1, off);
        }
        if (sl == 0) {
            l0 += b2_0; l1 += b2_1;
            float m = fmaxf(l0, l1);
            float e0 = __expf(l0 - m), e1 = __expf(l1 - m);
            float inv = 1.f / (e0 + e1);
            float p0 = e0 * inv, p1 = e1 * inv;
            float mm = fmaxf(p0, p1);
            float lse = mm + __logf(__expf(p0 - mm) + __expf(p1 - mm));
            int lab = __ldg(labels + p);
            float pl = lab ? p1 : p0;
            lsum += (lse - pl);
        }

        ua = na; ub = nb;
        p = pn;
    }

    lsum += __shfl_down_sync(0xFFFFFFFFu, lsum, 16);
    __shared__ float ssum[32];
    if (lane == 0) ssum[wib] = lsum;
    __syncthreads();
    if (threadIdx.x == 0) {
        float s = 0.f;
        for (int w = 0; w < warpsPerBlock; w++) s += ssum[w];
        atomicAdd(out, s / (float)B);
    }
}

// ---------------------------------------------------------------------------
extern "C" void kernel_launch(void* const* d_in, const int* in_sizes, int n_in,
                              void* d_out, int out_size) {
    const int*   pairs     = (const int*)d_in[0];
    const int*   labels    = (const int*)d_in[1];
    const int*   neighbors = (const int*)d_in[2];
    const float* embedding = (const float*)d_in[3];
    const float* W1        = (const float*)d_in[4];
    const float* b1        = (const float*)d_in[5];
    const float* W2        = (const float*)d_in[6];
    const float* b2        = (const float*)d_in[7];

    int B = in_sizes[0] / 2;
    int N = in_sizes[2] / KNBR;

    __half *E, *H1, *C, *Wh;
    cudaGetSymbolAddress((void**)&E,  g_E);
    cudaGetSymbolAddress((void**)&H1, g_H1);
    cudaGetSymbolAddress((void**)&C,  g_C);
    cudaGetSymbolAddress((void**)&Wh, g_Wh);

    float* out = (float*)d_out;

    // PREP: embedding fp16 convert + Wcat^T + zero loss (one launch)
    int n4 = N * DIM / 4;
    prep_kernel<<<(n4 + 255) / 256, 256>>>(embedding, E, n4, W1, Wh, out, out_size);

    // Aggregation layer 1
    int aggBlocks = (N / 2 + 7) / 8;
    agg_kernel<<<aggBlocks, 256>>>(E, neighbors, H1, N);

    // Fused agg layer 2 + projection GEMM (cp.async staged, 1 CTA/SM)
    size_t smem = (size_t)(384 * HSW) * 4 + 4096 + 3 * STAGE_BYTES;  // 206848 B
    cudaFuncSetAttribute(agg_gemm_kernel, cudaFuncAttributeMaxDynamicSharedMemorySize, (int)smem);
    agg_gemm_kernel<<<148, 512, smem>>>(H1, neighbors, Wh, C, N);

    // Pair loss (2 pairs per warp, pipelined grid-stride)
    pair_kernel<<<1184, 256>>>(pairs, labels, C, b1, W2, b2, out, B);
}

// round 16
// speedup vs baseline: 1.1307x; 1.1307x over previous
#include <cuda_runtime.h>
#include <cuda_fp16.h>
#include <cuda_bf16.h>
#include <math.h>

#define NMAX 50000
#define DIM 128
#define KNBR 16
#define HSW 68   // smem row stride in 32-bit words (64 data + 4 pad; 68%32==4)

// Scratch (static device globals — no allocation allowed)
__device__ __half g_E [(size_t)NMAX * DIM];
__device__ __half g_H1[(size_t)NMAX * DIM];
__device__ __half g_C [(size_t)NMAX * 2 * DIM];
__device__ __half g_Wh[256 * 128];   // Wcat^T as [n][k] fp16, row-major

// ---------------------------------------------------------------------------
// PREP: fp32->fp16 embedding convert + Wcat^T fp16 prep + zero loss accum.
// ---------------------------------------------------------------------------
__global__ void prep_kernel(const float* __restrict__ in, __half* __restrict__ out,
                            int n4, const float* __restrict__ W1,
                            __half* __restrict__ Wh,
                            float* __restrict__ loss_out, int loss_n) {
    int i = blockIdx.x * blockDim.x + threadIdx.x;
    if (blockIdx.x == 0 && threadIdx.x < (unsigned)loss_n) loss_out[threadIdx.x] = 0.f;
    if (i < n4) {
        float4 v = __ldg((const float4*)in + i);
        __half2 lo = __floats2half2_rn(v.x, v.y);
        __half2 hi = __floats2half2_rn(v.z, v.w);
        uint2 u;
        u.x = *(unsigned*)&lo;
        u.y = *(unsigned*)&hi;
        ((uint2*)out)[i] = u;
    }
    if (i < 256 * 128) {   // Wcat^T: Wh[n][k] = W1[r][c], n = c + (r>>7)*128, k = r&127
        int r = i >> 7;
        int c = i & 127;
        float v = __ldg(W1 + i);
        int k = r & 127;
        int n = c + ((r >> 7) << 7);
        Wh[n * 128 + k] = __float2half_rn(v);
    }
}

// ---------------------------------------------------------------------------
// Mean neighbor aggregation (layer 1), fp16: warp = 2 nodes, HADD2 accumulate.
// ---------------------------------------------------------------------------
__global__ void agg_kernel(const __half* __restrict__ in,
                           const int* __restrict__ nbr,
                           __half* __restrict__ out, int N) {
    int gw = (blockIdx.x * blockDim.x + threadIdx.x) >> 5;
    int lane = threadIdx.x & 31;
    int node = gw * 2 + (lane >> 4);
    if (node >= N) return;
    int sl = lane & 15;
    const int* nb = nbr + (size_t)node * KNBR;
    const uint4* in16 = (const uint4*)in;
    __half2 z = __float2half2_rn(0.f);
    __half2 a0 = z, a1 = z, a2 = z, a3 = z;
#pragma unroll
    for (int k = 0; k < KNBR; k++) {
        int idx = __ldg(nb + k);
        uint4 v = __ldg(in16 + (size_t)idx * 16 + sl);
        a0 = __hadd2(a0, *(__half2*)&v.x);
        a1 = __hadd2(a1, *(__half2*)&v.y);
        a2 = __hadd2(a2, *(__half2*)&v.z);
        a3 = __hadd2(a3, *(__half2*)&v.w);
    }
    __half2 s = __float2half2_rn(1.0f / (float)KNBR);
    a0 = __hmul2(a0, s); a1 = __hmul2(a1, s);
    a2 = __hmul2(a2, s); a3 = __hmul2(a3, s);
    uint4 r;
    r.x = *(unsigned*)&a0; r.y = *(unsigned*)&a1;
    r.z = *(unsigned*)&a2; r.w = *(unsigned*)&a3;
    ((uint4*)out)[(size_t)node * 16 + sl] = r;
}

// ---------------------------------------------------------------------------
// fp16 MMA + ldmatrix helpers
// ---------------------------------------------------------------------------
__device__ __forceinline__ void mma_f16(float* d, const unsigned* a, const unsigned* b) {
    asm("mma.sync.aligned.m16n8k16.row.col.f32.f16.f16.f32 "
        "{%0,%1,%2,%3}, {%4,%5,%6,%7}, {%8,%9}, {%0,%1,%2,%3};"
        : "+f"(d[0]), "+f"(d[1]), "+f"(d[2]), "+f"(d[3])
        : "r"(a[0]), "r"(a[1]), "r"(a[2]), "r"(a[3]), "r"(b[0]), "r"(b[1]));
}

__device__ __forceinline__ void ldsm_x4(unsigned* r, unsigned addr) {
    asm volatile("ldmatrix.sync.aligned.m8n8.x4.shared.b16 {%0,%1,%2,%3}, [%4];"
                 : "=r"(r[0]), "=r"(r[1]), "=r"(r[2]), "=r"(r[3]) : "r"(addr));
}

// ---------------------------------------------------------------------------
// FUSED agg-layer-2 + projection GEMM with INTERLEAVED gather/MMA.
// (R13 structure — best known; unchanged.)
// ---------------------------------------------------------------------------
extern __shared__ unsigned s_dyn_u[];

__global__ __launch_bounds__(256, 2) void agg_gemm_kernel(const __half* __restrict__ H1,
                                                          const int* __restrict__ nbr,
                                                          const __half* __restrict__ Wh,
                                                          __half* __restrict__ C, int N) {
    unsigned* Ws  = s_dyn_u;                 // words; halves [256][136]
    unsigned* Hs0 = s_dyn_u + 256 * HSW;     // words; halves [64][136]
    unsigned* Hs1 = Hs0 + 64 * HSW;
    int t = threadIdx.x;
    int lane = t & 31;
    int warp = t >> 5;
    int mwarp = warp >> 2;
    int nwarp = warp & 3;
    int g  = lane >> 2;
    int tg = lane & 3;
    int n0 = nwarp * 64;

    {
        const uint4* W16 = (const uint4*)Wh;
#pragma unroll
        for (int j = 0; j < 16; j++) {
            int i = t + j * 256;
            int n = i >> 4;
            int q = i & 15;
            uint4 v = __ldg(W16 + i);
            *(uint4*)(Ws + n * HSW + q * 4) = v;
        }
    }

    unsigned hs0_b = (unsigned)__cvta_generic_to_shared(Hs0);
    unsigned hs1_b = (unsigned)__cvta_generic_to_shared(Hs1);
    unsigned ws_base = (unsigned)__cvta_generic_to_shared(Ws);
    unsigned a_row  = lane & 15;
    unsigned a_koff = (lane >> 4) * 8;
    unsigned b_n    = (lane & 7) + ((lane >> 4) << 3);
    unsigned b_koff = ((lane >> 3) & 1) << 3;

    int numRowTiles = (N + 63) >> 6;
    int stride = gridDim.x;
    int rt0 = blockIdx.x;

    int agg_sub  = lane >> 4;
    int agg_sl   = lane & 15;
    const uint4* H1_16 = (const uint4*)H1;
    const __half2 hscale = __float2half2_rn(1.0f / (float)KNBR);
    const __half2 hzero  = __float2half2_rn(0.f);

    // Prologue: aggregate first tile into Hs0
    if (rt0 < numRowTiles) {
        int row0 = rt0 * 64;
#pragma unroll
        for (int round = 0; round < 4; round++) {
            int r_local = round * 16 + warp * 2 + agg_sub;
            int node = row0 + r_local;
            __half2 a0 = hzero, a1 = hzero, a2 = hzero, a3 = hzero;
            if (node < N) {
                const int* nb = nbr + (size_t)node * KNBR;
#pragma unroll
                for (int k = 0; k < KNBR; k++) {
                    int idx = __ldg(nb + k);
                    uint4 v = __ldg(H1_16 + (size_t)idx * 16 + agg_sl);
                    a0 = __hadd2(a0, *(__half2*)&v.x);
                    a1 = __hadd2(a1, *(__half2*)&v.y);
                    a2 = __hadd2(a2, *(__half2*)&v.z);
                    a3 = __hadd2(a3, *(__half2*)&v.w);
                }
                a0 = __hmul2(a0, hscale); a1 = __hmul2(a1, hscale);
                a2 = __hmul2(a2, hscale); a3 = __hmul2(a3, hscale);
            }
            uint4 r;
            r.x = *(unsigned*)&a0; r.y = *(unsigned*)&a1;
            r.z = *(unsigned*)&a2; r.w = *(unsigned*)&a3;
            *(uint4*)(Hs0 + r_local * HSW + agg_sl * 4) = r;
        }
    }

    int cur = 0;
    for (int rt = rt0; rt < numRowTiles; rt += stride) {
        int row0 = rt * 64;
        __syncthreads();

        unsigned hs_base = cur ? hs1_b : hs0_b;
        unsigned* Hn = cur ? Hs0 : Hs1;

        int rtn = rt + stride;
        const bool has_next = (rtn < numRowTiles);
        int rown0 = rtn * 64;

        int4 nb_all = make_int4(0, 0, 0, 0);
        if (has_next) {
            int L = lane & 15;
            int node_L = rown0 + (L >> 2) * 16 + warp * 2 + agg_sub;
            int cn = node_L < N ? node_L : N - 1;
            nb_all = __ldg((const int4*)(nbr + (size_t)cn * KNBR) + (L & 3));
        }

        float acc[2][8][4];
#pragma unroll
        for (int mf = 0; mf < 2; mf++)
#pragma unroll
            for (int nf = 0; nf < 8; nf++)
#pragma unroll
                for (int e = 0; e < 4; e++) acc[mf][nf][e] = 0.f;

        __half2 ga0 = hzero, ga1 = hzero, ga2 = hzero, ga3 = hzero;
        uint4 vb[4];

        if (has_next) {
            int src = (lane & 16);
            int i0 = __shfl_sync(0xFFFFFFFFu, nb_all.x, src);
            int i1 = __shfl_sync(0xFFFFFFFFu, nb_all.y, src);
            int i2 = __shfl_sync(0xFFFFFFFFu, nb_all.z, src);
            int i3 = __shfl_sync(0xFFFFFFFFu, nb_all.w, src);
            vb[0] = __ldg(H1_16 + (size_t)i0 * 16 + agg_sl);
            vb[1] = __ldg(H1_16 + (size_t)i1 * 16 + agg_sl);
            vb[2] = __ldg(H1_16 + (size_t)i2 * 16 + agg_sl);
            vb[3] = __ldg(H1_16 + (size_t)i3 * 16 + agg_sl);
        }

#pragma unroll
        for (int kk = 0; kk < 8; kk++) {
            unsigned k0 = kk * 16;
            unsigned af0[4], af1[4];
            ldsm_x4(af0, hs_base + ((mwarp * 32 + a_row) * (2 * HSW) + k0 + a_koff) * 2);
            ldsm_x4(af1, hs_base + ((mwarp * 32 + 16 + a_row) * (2 * HSW) + k0 + a_koff) * 2);
            unsigned b[8][2];
#pragma unroll
            for (int j = 0; j < 4; j++) {
                unsigned addr = ws_base +
                    ((n0 + j * 16 + b_n) * (2 * HSW) + k0 + b_koff) * 2;
                unsigned r[4];
                ldsm_x4(r, addr);
                b[2 * j][0] = r[0]; b[2 * j][1] = r[1];
                b[2 * j + 1][0] = r[2]; b[2 * j + 1][1] = r[3];
            }

#pragma unroll
            for (int nf = 0; nf < 8; nf++)
                mma_f16(acc[0][nf], af0, b[nf]);

            if (has_next) {
                int s = 2 * kk;
                int node_s = rown0 + (s >> 2) * 16 + warp * 2 + agg_sub;
                if (node_s < N) {
#pragma unroll
                    for (int j = 0; j < 4; j++) {
                        ga0 = __hadd2(ga0, *(__half2*)&vb[j].x);
                        ga1 = __hadd2(ga1, *(__half2*)&vb[j].y);
                        ga2 = __hadd2(ga2, *(__half2*)&vb[j].z);
                        ga3 = __hadd2(ga3, *(__half2*)&vb[j].w);
                    }
                }
                int s1 = s + 1;
                int src = (lane & 16) + s1;
                int i0 = __shfl_sync(0xFFFFFFFFu, nb_all.x, src);
                int i1 = __shfl_sync(0xFFFFFFFFu, nb_all.y, src);
                int i2 = __shfl_sync(0xFFFFFFFFu, nb_all.z, src);
                int i3 = __shfl_sync(0xFFFFFFFFu, nb_all.w, src);
                vb[0] = __ldg(H1_16 + (size_t)i0 * 16 + agg_sl);
                vb[1] = __ldg(H1_16 + (size_t)i1 * 16 + agg_sl);
                vb[2] = __ldg(H1_16 + (size_t)i2 * 16 + agg_sl);
                vb[3] = __ldg(H1_16 + (size_t)i3 * 16 + agg_sl);
            }

#pragma unroll
            for (int nf = 0; nf < 8; nf++)
                mma_f16(acc[1][nf], af1, b[nf]);

            if (has_next) {
                int s = 2 * kk + 1;
                int node_s = rown0 + (s >> 2) * 16 + warp * 2 + agg_sub;
                if (node_s < N) {
#pragma unroll
                    for (int j = 0; j < 4; j++) {
                        ga0 = __hadd2(ga0, *(__half2*)&vb[j].x);
                        ga1 = __hadd2(ga1, *(__half2*)&vb[j].y);
                        ga2 = __hadd2(ga2, *(__half2*)&vb[j].z);
                        ga3 = __hadd2(ga3, *(__half2*)&vb[j].w);
                    }
                }
                if ((s & 3) == 3) {
                    int r_local = (s >> 2) * 16 + warp * 2 + agg_sub;
                    __half2 r0 = __hmul2(ga0, hscale);
                    __half2 r1 = __hmul2(ga1, hscale);
                    __half2 r2 = __hmul2(ga2, hscale);
                    __half2 r3 = __hmul2(ga3, hscale);
                    uint4 r;
                    r.x = *(unsigned*)&r0; r.y = *(unsigned*)&r1;
                    r.z = *(unsigned*)&r2; r.w = *(unsigned*)&r3;
                    *(uint4*)(Hn + r_local * HSW + agg_sl * 4) = r;
                    ga0 = hzero; ga1 = hzero; ga2 = hzero; ga3 = hzero;
                }
                if (kk < 7) {
                    int s2 = s + 1;
                    int src = (lane & 16) + s2;
                    int i0 = __shfl_sync(0xFFFFFFFFu, nb_all.x, src);
                    int i1 = __shfl_sync(0xFFFFFFFFu, nb_all.y, src);
                    int i2 = __shfl_sync(0xFFFFFFFFu, nb_all.z, src);
                    int i3 = __shfl_sync(0xFFFFFFFFu, nb_all.w, src);
                    vb[0] = __ldg(H1_16 + (size_t)i0 * 16 + agg_sl);
                    vb[1] = __ldg(H1_16 + (size_t)i1 * 16 + agg_sl);
                    vb[2] = __ldg(H1_16 + (size_t)i2 * 16 + agg_sl);
                    vb[3] = __ldg(H1_16 + (size_t)i3 * 16 + agg_sl);
                }
            }
        }

        unsigned* C32 = (unsigned*)C;
#pragma unroll
        for (int mf = 0; mf < 2; mf++) {
            int r_lo = row0 + mwarp * 32 + mf * 16 + g;
            int r_hi = r_lo + 8;
#pragma unroll
            for (int nf = 0; nf < 8; nf++) {
                int colh = (n0 + nf * 8 + tg * 2) >> 1;
                if (r_lo < N) {
                    __half2 h = __floats2half2_rn(acc[mf][nf][0], acc[mf][nf][1]);
                    C32[(size_t)r_lo * 128 + colh] = *(unsigned*)&h;
                }
                if (r_hi < N) {
                    __half2 h = __floats2half2_rn(acc[mf][nf][2], acc[mf][nf][3]);
                    C32[(size_t)r_hi * 128 + colh] = *(unsigned*)&h;
                }
            }
        }
        cur ^= 1;
    }
}

// ---------------------------------------------------------------------------
// Per-pair loss: one warp = TWO pairs, lean state, DEPTH-2 software pipeline
// (two pending C-row buffers; loads for iteration i+2 issued during i).
// ---------------------------------------------------------------------------
__global__ void pair_kernel(const int* __restrict__ pairs,
                            const int* __restrict__ labels,
                            const __half* __restrict__ C,
                            const float* __restrict__ b1,
                            const float* __restrict__ W2,
                            const float* __restrict__ b2,
                            float* __restrict__ out, int B) {
    int lane = threadIdx.x & 31;
    int sl = lane & 15;
    int side = lane >> 4;
    int wib = threadIdx.x >> 5;
    int warpsPerBlock = blockDim.x >> 5;
    int gwarp = blockIdx.x * warpsPerBlock + wib;
    int nwarps = gridDim.x * warpsPerBlock;
    int step = nwarps * 2;

    float4 b_lo = __ldg((const float4*)b1 + 2 * sl);
    float4 b_hi = __ldg((const float4*)b1 + 2 * sl + 1);
    float bias[8] = {b_lo.x, b_lo.y, b_lo.z, b_lo.w, b_hi.x, b_hi.y, b_hi.z, b_hi.w};
    float w20[8], w21[8];
#pragma unroll
    for (int q = 0; q < 8; q++) {
        w20[q] = __ldg(W2 + (sl * 8 + q) * 2 + 0);
        w21[q] = __ldg(W2 + (sl * 8 + q) * 2 + 1);
    }
    float b2_0 = __ldg(b2 + 0), b2_1 = __ldg(b2 + 1);

    const uint4* C16 = (const uint4*)C;
    float lsum = 0.f;

    int p = gwarp * 2 + side;
    uint4 ua0, ub0, ua1, ub1;
    if (p < B) {
        int src = __ldg(pairs + 2 * p);
        int dst = __ldg(pairs + 2 * p + 1);
        ua0 = __ldg(C16 + (size_t)src * 32 + sl);
        ub0 = __ldg(C16 + (size_t)dst * 32 + 16 + sl);
    }
    if (p + step < B) {
        int src = __ldg(pairs + 2 * (p + step));
        int dst = __ldg(pairs + 2 * (p + step) + 1);
        ua1 = __ldg(C16 + (size_t)src * 32 + sl);
        ub1 = __ldg(C16 + (size_t)dst * 32 + 16 + sl);
    }

    while (p < B) {
        // Issue loads for iteration i+2
        int pn2 = p + 2 * step;
        uint4 na, nb;
        if (pn2 < B) {
            int nsrc = __ldg(pairs + 2 * pn2);
            int ndst = __ldg(pairs + 2 * pn2 + 1);
            na = __ldg(C16 + (size_t)nsrc * 32 + sl);
            nb = __ldg(C16 + (size_t)ndst * 32 + 16 + sl);
        }

        float l0 = 0.f, l1 = 0.f;
        const unsigned* au = (const unsigned*)&ua0;
        const unsigned* bu = (const unsigned*)&ub0;
#pragma unroll
        for (int c = 0; c < 4; c++) {
            float2 af = __half22float2(*(__half2*)&au[c]);
            float2 bf = __half22float2(*(__half2*)&bu[c]);
            float h0 = fmaxf(af.x + bf.x + bias[2 * c], 0.f);
            float h1 = fmaxf(af.y + bf.y + bias[2 * c + 1], 0.f);
            l0 += h0 * w20[2 * c] + h1 * w20[2 * c + 1];
            l1 += h0 * w21[2 * c] + h1 * w21[2 * c + 1];
        }
#pragma unroll
        for (int off = 8; off > 0; off >>= 1) {
            l0 += __shfl_xor_sync(0xFFFFFFFFu, l0, off);
            l1 += __shfl_xor_sync(0xFFFFFFFFu, l1, off);
        }
        if (sl == 0) {
            l0 += b2_0; l1 += b2_1;
            float m = fmaxf(l0, l1);
            float e0 = __expf(l0 - m), e1 = __expf(l1 - m);
            float inv = 1.f / (e0 + e1);
            float p0 = e0 * inv, p1 = e1 * inv;
            float mm = fmaxf(p0, p1);
            float lse = mm + __logf(__expf(p0 - mm) + __expf(p1 - mm));
            int lab = __ldg(labels + p);
            float pl = lab ? p1 : p0;
            lsum += (lse - pl);
        }

        ua0 = ua1; ub0 = ub1;
        ua1 = na;  ub1 = nb;
        p += step;
    }

    lsum += __shfl_down_sync(0xFFFFFFFFu, lsum, 16);
    __shared__ float ssum[32];
    if (lane == 0) ssum[wib] = lsum;
    __syncthreads();
    if (threadIdx.x == 0) {
        float s = 0.f;
        for (int w = 0; w < warpsPerBlock; w++) s += ssum[w];
        atomicAdd(out, s / (float)B);
    }
}

// ---------------------------------------------------------------------------
extern "C" void kernel_launch(void* const* d_in, const int* in_sizes, int n_in,
                              void* d_out, int out_size) {
    const int*   pairs     = (const int*)d_in[0];
    const int*   labels    = (const int*)d_in[1];
    const int*   neighbors = (const int*)d_in[2];
    const float* embedding = (const float*)d_in[3];
    const float* W1        = (const float*)d_in[4];
    const float* b1        = (const float*)d_in[5];
    const float* W2        = (const float*)d_in[6];
    const float* b2        = (const float*)d_in[7];

    int B = in_sizes[0] / 2;
    int N = in_sizes[2] / KNBR;

    __half *E, *H1, *C, *Wh;
    cudaGetSymbolAddress((void**)&E,  g_E);
    cudaGetSymbolAddress((void**)&H1, g_H1);
    cudaGetSymbolAddress((void**)&C,  g_C);
    cudaGetSymbolAddress((void**)&Wh, g_Wh);

    float* out = (float*)d_out;

    // PREP: embedding fp16 convert + Wcat^T + zero loss (one launch)
    int n4 = N * DIM / 4;
    prep_kernel<<<(n4 + 255) / 256, 256>>>(embedding, E, n4, W1, Wh, out, out_size);

    // Aggregation layer 1
    int aggBlocks = (N / 2 + 7) / 8;
    agg_kernel<<<aggBlocks, 256>>>(E, neighbors, H1, N);

    // Fused agg layer 2 + projection GEMM (interleaved, 2 CTAs/SM)
    size_t smem = (size_t)(256 * HSW + 2 * 64 * HSW) * sizeof(unsigned);  // 104448 B
    cudaFuncSetAttribute(agg_gemm_kernel, cudaFuncAttributeMaxDynamicSharedMemorySize, (int)smem);
    agg_gemm_kernel<<<296, 256, smem>>>(H1, neighbors, Wh, C, N);

    // Pair loss (2 pairs per warp, depth-2 pipelined grid-stride)
    pair_kernel<<<1184, 256>>>(pairs, labels, C, b1, W2, b2, out, B);
}

// round 17
// speedup vs baseline: 1.1466x; 1.0141x over previous
#include <cuda_runtime.h>
#include <cuda_fp16.h>
#include <cuda_bf16.h>
#include <math.h>

#define NMAX 50000
#define DIM 128
#define KNBR 16
#define HSW 68   // smem row stride in 32-bit words (64 data + 4 pad; 68%32==4)

// Scratch (static device globals — no allocation allowed)
__device__ __half g_E [(size_t)NMAX * DIM];
__device__ __half g_H1[(size_t)NMAX * DIM];
__device__ __half g_C [(size_t)NMAX * 2 * DIM];
__device__ __half g_Wh[256 * 128];   // Wcat^T as [n][k] fp16, row-major

// ---------------------------------------------------------------------------
// PREP: fp32->fp16 embedding convert + Wcat^T fp16 prep + zero loss accum.
// ---------------------------------------------------------------------------
__global__ void prep_kernel(const float* __restrict__ in, __half* __restrict__ out,
                            int n4, const float* __restrict__ W1,
                            __half* __restrict__ Wh,
                            float* __restrict__ loss_out, int loss_n) {
    int i = blockIdx.x * blockDim.x + threadIdx.x;
    if (blockIdx.x == 0 && threadIdx.x < (unsigned)loss_n) loss_out[threadIdx.x] = 0.f;
    if (i < n4) {
        float4 v = __ldg((const float4*)in + i);
        __half2 lo = __floats2half2_rn(v.x, v.y);
        __half2 hi = __floats2half2_rn(v.z, v.w);
        uint2 u;
        u.x = *(unsigned*)&lo;
        u.y = *(unsigned*)&hi;
        ((uint2*)out)[i] = u;
    }
    if (i < 256 * 128) {
        int r = i >> 7;
        int c = i & 127;
        float v = __ldg(W1 + i);
        int k = r & 127;
        int n = c + ((r >> 7) << 7);
        Wh[n * 128 + k] = __float2half_rn(v);
    }
}

// ---------------------------------------------------------------------------
// Mean neighbor aggregation (layer 1), fp16: warp = 2 nodes, HADD2 accumulate.
// ---------------------------------------------------------------------------
__global__ void agg_kernel(const __half* __restrict__ in,
                           const int* __restrict__ nbr,
                           __half* __restrict__ out, int N) {
    int gw = (blockIdx.x * blockDim.x + threadIdx.x) >> 5;
    int lane = threadIdx.x & 31;
    int node = gw * 2 + (lane >> 4);
    if (node >= N) return;
    int sl = lane & 15;
    const int* nb = nbr + (size_t)node * KNBR;
    const uint4* in16 = (const uint4*)in;
    __half2 z = __float2half2_rn(0.f);
    __half2 a0 = z, a1 = z, a2 = z, a3 = z;
#pragma unroll
    for (int k = 0; k < KNBR; k++) {
        int idx = __ldg(nb + k);
        uint4 v = __ldg(in16 + (size_t)idx * 16 + sl);
        a0 = __hadd2(a0, *(__half2*)&v.x);
        a1 = __hadd2(a1, *(__half2*)&v.y);
        a2 = __hadd2(a2, *(__half2*)&v.z);
        a3 = __hadd2(a3, *(__half2*)&v.w);
    }
    __half2 s = __float2half2_rn(1.0f / (float)KNBR);
    a0 = __hmul2(a0, s); a1 = __hmul2(a1, s);
    a2 = __hmul2(a2, s); a3 = __hmul2(a3, s);
    uint4 r;
    r.x = *(unsigned*)&a0; r.y = *(unsigned*)&a1;
    r.z = *(unsigned*)&a2; r.w = *(unsigned*)&a3;
    ((uint4*)out)[(size_t)node * 16 + sl] = r;
}

// ---------------------------------------------------------------------------
// fp16 MMA + ldmatrix helpers
// ---------------------------------------------------------------------------
__device__ __forceinline__ void mma_f16(float* d, const unsigned* a, const unsigned* b) {
    asm("mma.sync.aligned.m16n8k16.row.col.f32.f16.f16.f32 "
        "{%0,%1,%2,%3}, {%4,%5,%6,%7}, {%8,%9}, {%0,%1,%2,%3};"
        : "+f"(d[0]), "+f"(d[1]), "+f"(d[2]), "+f"(d[3])
        : "r"(a[0]), "r"(a[1]), "r"(a[2]), "r"(a[3]), "r"(b[0]), "r"(b[1]));
}

__device__ __forceinline__ void ldsm_x4(unsigned* r, unsigned addr) {
    asm volatile("ldmatrix.sync.aligned.m8n8.x4.shared.b16 {%0,%1,%2,%3}, [%4];"
                 : "=r"(r[0]), "=r"(r[1]), "=r"(r[2]), "=r"(r[3]) : "r"(addr));
}

// ---------------------------------------------------------------------------
// FUSED agg-layer-2 + projection GEMM, 512-thread / 1 CTA-per-SM variant.
// 16 warps: 4(m) x 4(n), warp tile 16x64, 32-reg acc. Warp gathers 4 rows of
// the NEXT tile via a 2-deep register pipeline (substep s+2 in flight while s
// is consumed) woven between MMA half-chunks. One __syncthreads per tile.
// Smem: Ws [256][136h] 69.6KB + Hs 2x[64][136h] 34.8KB = 104.4KB.
// ---------------------------------------------------------------------------
extern __shared__ unsigned s_dyn_u[];

__global__ __launch_bounds__(512, 1) void agg_gemm_kernel(const __half* __restrict__ H1,
                                                          const int* __restrict__ nbr,
                                                          const __half* __restrict__ Wh,
                                                          __half* __restrict__ C, int N) {
    unsigned* Ws  = s_dyn_u;                 // words; halves [256][136]
    unsigned* Hs0 = s_dyn_u + 256 * HSW;     // words; halves [64][136]
    unsigned* Hs1 = Hs0 + 64 * HSW;
    int t = threadIdx.x;
    int lane = t & 31;
    int warp = t >> 5;          // 0..15
    int mwarp = warp >> 2;      // 0..3
    int nwarp = warp & 3;       // 0..3
    int g  = lane >> 2;
    int tg = lane & 3;
    int n0 = nwarp * 64;

    // Fill Ws (4096 uint4, 8 per thread)
    {
        const uint4* W16 = (const uint4*)Wh;
#pragma unroll
        for (int j = 0; j < 8; j++) {
            int i = t + j * 512;
            int n = i >> 4;
            int q = i & 15;
            uint4 v = __ldg(W16 + i);
            *(uint4*)(Ws + n * HSW + q * 4) = v;
        }
    }

    unsigned hs0_b = (unsigned)__cvta_generic_to_shared(Hs0);
    unsigned hs1_b = (unsigned)__cvta_generic_to_shared(Hs1);
    unsigned ws_base = (unsigned)__cvta_generic_to_shared(Ws);
    unsigned a_row  = lane & 15;
    unsigned a_koff = (lane >> 4) * 8;
    unsigned b_n    = (lane & 7) + ((lane >> 4) << 3);
    unsigned b_koff = ((lane >> 3) & 1) << 3;

    int numRowTiles = (N + 63) >> 6;
    int stride = gridDim.x;
    int rt0 = blockIdx.x;

    int agg_sub  = lane >> 4;   // half-warp: which of the warp's 2 rows/round
    int agg_sl   = lane & 15;   // 16 lanes cover one 256B row
    const uint4* H1_16 = (const uint4*)H1;
    const __half2 hscale = __float2half2_rn(1.0f / (float)KNBR);
    const __half2 hzero  = __float2half2_rn(0.f);

    // Prologue: aggregate first tile into Hs0 (warp owns rows round*32+warp*2+sub)
    if (rt0 < numRowTiles) {
        int row0 = rt0 * 64;
#pragma unroll
        for (int round = 0; round < 2; round++) {
            int r_local = round * 32 + warp * 2 + agg_sub;
            int node = row0 + r_local;
            __half2 a0 = hzero, a1 = hzero, a2 = hzero, a3 = hzero;
            if (node < N) {
                const int* nb = nbr + (size_t)node * KNBR;
#pragma unroll
                for (int k = 0; k < KNBR; k++) {
                    int idx = __ldg(nb + k);
                    uint4 v = __ldg(H1_16 + (size_t)idx * 16 + agg_sl);
                    a0 = __hadd2(a0, *(__half2*)&v.x);
                    a1 = __hadd2(a1, *(__half2*)&v.y);
                    a2 = __hadd2(a2, *(__half2*)&v.z);
                    a3 = __hadd2(a3, *(__half2*)&v.w);
                }
                a0 = __hmul2(a0, hscale); a1 = __hmul2(a1, hscale);
                a2 = __hmul2(a2, hscale); a3 = __hmul2(a3, hscale);
            }
            uint4 r;
            r.x = *(unsigned*)&a0; r.y = *(unsigned*)&a1;
            r.z = *(unsigned*)&a2; r.w = *(unsigned*)&a3;
            *(uint4*)(Hs0 + r_local * HSW + agg_sl * 4) = r;
        }
    }

    int cur = 0;
    for (int rt = rt0; rt < numRowTiles; rt += stride) {
        int row0 = rt * 64;
        __syncthreads();   // Hs[cur] complete; Hs[nxt] free everywhere

        unsigned hs_base = cur ? hs1_b : hs0_b;
        unsigned* Hn = cur ? Hs0 : Hs1;

        int rtn = rt + stride;
        const bool has_next = (rtn < numRowTiles);
        int rown0 = rtn * 64;

        // Prefetch next-tile neighbor indices: lane L (&15, L<8 meaningful)
        // holds int4 for substep s=L: round=L>>2, quarter=L&3, of its half's row.
        int4 nb_all = make_int4(0, 0, 0, 0);
        if (has_next) {
            int L = lane & 15;
            int node_L = rown0 + (L >> 2) * 32 + warp * 2 + agg_sub;
            int cn = node_L < N ? node_L : N - 1;
            nb_all = __ldg((const int4*)(nbr + (size_t)cn * KNBR) + (L & 3));
        }

        float acc[8][4];
#pragma unroll
        for (int nf = 0; nf < 8; nf++)
#pragma unroll
            for (int e = 0; e < 4; e++) acc[nf][e] = 0.f;

        __half2 ga0 = hzero, ga1 = hzero, ga2 = hzero, ga3 = hzero;
        uint4 vb0[4], vb1[4];   // 2-deep substep buffers

        // Issue substeps 0 and 1
        if (has_next) {
            {
                int src = (lane & 16);      // substep 0
                int i0 = __shfl_sync(0xFFFFFFFFu, nb_all.x, src);
                int i1 = __shfl_sync(0xFFFFFFFFu, nb_all.y, src);
                int i2 = __shfl_sync(0xFFFFFFFFu, nb_all.z, src);
                int i3 = __shfl_sync(0xFFFFFFFFu, nb_all.w, src);
                vb0[0] = __ldg(H1_16 + (size_t)i0 * 16 + agg_sl);
                vb0[1] = __ldg(H1_16 + (size_t)i1 * 16 + agg_sl);
                vb0[2] = __ldg(H1_16 + (size_t)i2 * 16 + agg_sl);
                vb0[3] = __ldg(H1_16 + (size_t)i3 * 16 + agg_sl);
            }
            {
                int src = (lane & 16) + 1;  // substep 1
                int i0 = __shfl_sync(0xFFFFFFFFu, nb_all.x, src);
                int i1 = __shfl_sync(0xFFFFFFFFu, nb_all.y, src);
                int i2 = __shfl_sync(0xFFFFFFFFu, nb_all.z, src);
                int i3 = __shfl_sync(0xFFFFFFFFu, nb_all.w, src);
                vb1[0] = __ldg(H1_16 + (size_t)i0 * 16 + agg_sl);
                vb1[1] = __ldg(H1_16 + (size_t)i1 * 16 + agg_sl);
                vb1[2] = __ldg(H1_16 + (size_t)i2 * 16 + agg_sl);
                vb1[3] = __ldg(H1_16 + (size_t)i3 * 16 + agg_sl);
            }
        }

#pragma unroll
        for (int kk = 0; kk < 8; kk++) {
            unsigned k0 = kk * 16;
            unsigned af[4];
            ldsm_x4(af, hs_base + ((mwarp * 16 + a_row) * (2 * HSW) + k0 + a_koff) * 2);
            unsigned b[8][2];
#pragma unroll
            for (int j = 0; j < 4; j++) {
                unsigned addr = ws_base +
                    ((n0 + j * 16 + b_n) * (2 * HSW) + k0 + b_koff) * 2;
                unsigned r[4];
                ldsm_x4(r, addr);
                b[2 * j][0] = r[0]; b[2 * j][1] = r[1];
                b[2 * j + 1][0] = r[2]; b[2 * j + 1][1] = r[3];
            }

            // First half of MMAs
#pragma unroll
            for (int nf = 0; nf < 4; nf++)
                mma_f16(acc[nf], af, b[nf]);

            // Consume substep kk; finalize row at quarter 3; issue substep kk+2
            if (has_next) {
                uint4* vb = (kk & 1) ? vb1 : vb0;
                int s = kk;
                int node_s = rown0 + (s >> 2) * 32 + warp * 2 + agg_sub;
                if (node_s < N) {
#pragma unroll
                    for (int j = 0; j < 4; j++) {
                        ga0 = __hadd2(ga0, *(__half2*)&vb[j].x);
                        ga1 = __hadd2(ga1, *(__half2*)&vb[j].y);
                        ga2 = __hadd2(ga2, *(__half2*)&vb[j].z);
                        ga3 = __hadd2(ga3, *(__half2*)&vb[j].w);
                    }
                }
                if ((s & 3) == 3) {   // row (round = s>>2) complete
                    int r_local = (s >> 2) * 32 + warp * 2 + agg_sub;
                    __half2 r0 = __hmul2(ga0, hscale);
                    __half2 r1 = __hmul2(ga1, hscale);
                    __half2 r2 = __hmul2(ga2, hscale);
                    __half2 r3 = __hmul2(ga3, hscale);
                    uint4 r;
                    r.x = *(unsigned*)&r0; r.y = *(unsigned*)&r1;
                    r.z = *(unsigned*)&r2; r.w = *(unsigned*)&r3;
                    *(uint4*)(Hn + r_local * HSW + agg_sl * 4) = r;
                    ga0 = hzero; ga1 = hzero; ga2 = hzero; ga3 = hzero;
                }
                int s2 = kk + 2;
                if (s2 < 8) {
                    int src = (lane & 16) + s2;
                    int i0 = __shfl_sync(0xFFFFFFFFu, nb_all.x, src);
                    int i1 = __shfl_sync(0xFFFFFFFFu, nb_all.y, src);
                    int i2 = __shfl_sync(0xFFFFFFFFu, nb_all.z, src);
                    int i3 = __shfl_sync(0xFFFFFFFFu, nb_all.w, src);
                    vb[0] = __ldg(H1_16 + (size_t)i0 * 16 + agg_sl);
                    vb[1] = __ldg(H1_16 + (size_t)i1 * 16 + agg_sl);
                    vb[2] = __ldg(H1_16 + (size_t)i2 * 16 + agg_sl);
                    vb[3] = __ldg(H1_16 + (size_t)i3 * 16 + agg_sl);
                }
            }

            // Second half of MMAs
#pragma unroll
            for (int nf = 4; nf < 8; nf++)
                mma_f16(acc[nf], af, b[nf]);
        }

        // Epilogue -> fp16 C
        unsigned* C32 = (unsigned*)C;
        int r_lo = row0 + mwarp * 16 + g;
        int r_hi = r_lo + 8;
#pragma unroll
        for (int nf = 0; nf < 8; nf++) {
            int colh = (n0 + nf * 8 + tg * 2) >> 1;
            if (r_lo < N) {
                __half2 h = __floats2half2_rn(acc[nf][0], acc[nf][1]);
                C32[(size_t)r_lo * 128 + colh] = *(unsigned*)&h;
            }
            if (r_hi < N) {
                __half2 h = __floats2half2_rn(acc[nf][2], acc[nf][3]);
                C32[(size_t)r_hi * 128 + colh] = *(unsigned*)&h;
            }
        }
        cur ^= 1;
    }
}

// ---------------------------------------------------------------------------
// Per-pair loss: one warp = TWO pairs, lean state, depth-2 software pipeline.
// ---------------------------------------------------------------------------
__global__ void pair_kernel(const int* __restrict__ pairs,
                            const int* __restrict__ labels,
                            const __half* __restrict__ C,
                            const float* __restrict__ b1,
                            const float* __restrict__ W2,
                            const float* __restrict__ b2,
                            float* __restrict__ out, int B) {
    int lane = threadIdx.x & 31;
    int sl = lane & 15;
    int side = lane >> 4;
    int wib = threadIdx.x >> 5;
    int warpsPerBlock = blockDim.x >> 5;
    int gwarp = blockIdx.x * warpsPerBlock + wib;
    int nwarps = gridDim.x * warpsPerBlock;
    int step = nwarps * 2;

    float4 b_lo = __ldg((const float4*)b1 + 2 * sl);
    float4 b_hi = __ldg((const float4*)b1 + 2 * sl + 1);
    float bias[8] = {b_lo.x, b_lo.y, b_lo.z, b_lo.w, b_hi.x, b_hi.y, b_hi.z, b_hi.w};
    float w20[8], w21[8];
#pragma unroll
    for (int q = 0; q < 8; q++) {
        w20[q] = __ldg(W2 + (sl * 8 + q) * 2 + 0);
        w21[q] = __ldg(W2 + (sl * 8 + q) * 2 + 1);
    }
    float b2_0 = __ldg(b2 + 0), b2_1 = __ldg(b2 + 1);

    const uint4* C16 = (const uint4*)C;
    float lsum = 0.f;

    int p = gwarp * 2 + side;
    uint4 ua0, ub0, ua1, ub1;
    if (p < B) {
        int src = __ldg(pairs + 2 * p);
        int dst = __ldg(pairs + 2 * p + 1);
        ua0 = __ldg(C16 + (size_t)src * 32 + sl);
        ub0 = __ldg(C16 + (size_t)dst * 32 + 16 + sl);
    }
    if (p + step < B) {
        int src = __ldg(pairs + 2 * (p + step));
        int dst = __ldg(pairs + 2 * (p + step) + 1);
        ua1 = __ldg(C16 + (size_t)src * 32 + sl);
        ub1 = __ldg(C16 + (size_t)dst * 32 + 16 + sl);
    }

    while (p < B) {
        int pn2 = p + 2 * step;
        uint4 na, nb;
        if (pn2 < B) {
            int nsrc = __ldg(pairs + 2 * pn2);
            int ndst = __ldg(pairs + 2 * pn2 + 1);
            na = __ldg(C16 + (size_t)nsrc * 32 + sl);
            nb = __ldg(C16 + (size_t)ndst * 32 + 16 + sl);
        }

        float l0 = 0.f, l1 = 0.f;
        const unsigned* au = (const unsigned*)&ua0;
        const unsigned* bu = (const unsigned*)&ub0;
#pragma unroll
        for (int c = 0; c < 4; c++) {
            float2 af = __half22float2(*(__half2*)&au[c]);
            float2 bf = __half22float2(*(__half2*)&bu[c]);
            float h0 = fmaxf(af.x + bf.x + bias[2 * c], 0.f);
            float h1 = fmaxf(af.y + bf.y + bias[2 * c + 1], 0.f);
            l0 += h0 * w20[2 * c] + h1 * w20[2 * c + 1];
            l1 += h0 * w21[2 * c] + h1 * w21[2 * c + 1];
        }
#pragma unroll
        for (int off = 8; off > 0; off >>= 1) {
            l0 += __shfl_xor_sync(0xFFFFFFFFu, l0, off);
            l1 += __shfl_xor_sync(0xFFFFFFFFu, l1, off);
        }
        if (sl == 0) {
            l0 += b2_0; l1 += b2_1;
            float m = fmaxf(l0, l1);
            float e0 = __expf(l0 - m), e1 = __expf(l1 - m);
            float inv = 1.f / (e0 + e1);
            float p0 = e0 * inv, p1 = e1 * inv;
            float mm = fmaxf(p0, p1);
            float lse = mm + __logf(__expf(p0 - mm) + __expf(p1 - mm));
            int lab = __ldg(labels + p);
            float pl = lab ? p1 : p0;
            lsum += (lse - pl);
        }

        ua0 = ua1; ub0 = ub1;
        ua1 = na;  ub1 = nb;
        p += step;
    }

    lsum += __shfl_down_sync(0xFFFFFFFFu, lsum, 16);
    __shared__ float ssum[32];
    if (lane == 0) ssum[wib] = lsum;
    __syncthreads();
    if (threadIdx.x == 0) {
        float s = 0.f;
        for (int w = 0; w < warpsPerBlock; w++) s += ssum[w];
        atomicAdd(out, s / (float)B);
    }
}

// ---------------------------------------------------------------------------
extern "C" void kernel_launch(void* const* d_in, const int* in_sizes, int n_in,
                              void* d_out, int out_size) {
    const int*   pairs     = (const int*)d_in[0];
    const int*   labels    = (const int*)d_in[1];
    const int*   neighbors = (const int*)d_in[2];
    const float* embedding = (const float*)d_in[3];
    const float* W1        = (const float*)d_in[4];
    const float* b1        = (const float*)d_in[5];
    const float* W2        = (const float*)d_in[6];
    const float* b2        = (const float*)d_in[7];

    int B = in_sizes[0] / 2;
    int N = in_sizes[2] / KNBR;

    __half *E, *H1, *C, *Wh;
    cudaGetSymbolAddress((void**)&E,  g_E);
    cudaGetSymbolAddress((void**)&H1, g_H1);
    cudaGetSymbolAddress((void**)&C,  g_C);
    cudaGetSymbolAddress((void**)&Wh, g_Wh);

    float* out = (float*)d_out;

    // PREP: embedding fp16 convert + Wcat^T + zero loss (one launch)
    int n4 = N * DIM / 4;
    prep_kernel<<<(n4 + 255) / 256, 256>>>(embedding, E, n4, W1, Wh, out, out_size);

    // Aggregation layer 1
    int aggBlocks = (N / 2 + 7) / 8;
    agg_kernel<<<aggBlocks, 256>>>(E, neighbors, H1, N);

    // Fused agg layer 2 + projection GEMM (512 threads, 1 CTA/SM, 2-deep pipe)
    size_t smem = (size_t)(256 * HSW + 2 * 64 * HSW) * sizeof(unsigned);  // 104448 B
    cudaFuncSetAttribute(agg_gemm_kernel, cudaFuncAttributeMaxDynamicSharedMemorySize, (int)smem);
    agg_gemm_kernel<<<148, 512, smem>>>(H1, neighbors, Wh, C, N);

    // Pair loss (2 pairs per warp, depth-2 pipelined grid-stride)
    pair_kernel<<<1184, 256>>>(pairs, labels, C, b1, W2, b2, out, B);
}